// round 1
// baseline (speedup 1.0000x reference)
#include <cuda_runtime.h>
#include <math.h>
#include <stdint.h>

#define N_NODES 100000
#define N_EDGES 1600000
#define N_GRAPH 64
#define HID     128
#define NLAY    4
#define NCLS    16
#define NCANDE  100000
#define EMBW    512           // NLAY*HID
#define BN_EPSF 1e-5f

// ------------------------- persistent device scratch -------------------------
__device__ float g_emb[(size_t)N_NODES * EMBW];   // per-layer BN outputs, concatenated
__device__ float g_agg[(size_t)N_NODES * HID];
__device__ float g_z1 [(size_t)N_NODES * HID];
__device__ float g_z2 [(size_t)N_NODES * HID];
__device__ float g_P  [(size_t)NCANDE * 512];     // [P0 | P1]
__device__ float g_u  [(size_t)NCANDE * 256];
__device__ float g_u2 [(size_t)NCANDE * 128];
__device__ float g_stats[2 * HID];                // col sums, col sumsq
__device__ float g_gemb[N_GRAPH * EMBW];
__device__ float g_cnt [N_GRAPH];
__device__ float g_t1[N_GRAPH * 256];
__device__ float g_t2[N_GRAPH * 128];
__device__ float g_t3[N_GRAPH * 128];
__device__ float g_logits[N_GRAPH * NCLS];

// ------------------------------- small utils --------------------------------
__global__ void zero_kernel(float* p, int n) {
    int i = blockIdx.x * blockDim.x + threadIdx.x;
    if (i < n) p[i] = 0.f;
}

// agg[i,:] = (1+eps[l]) * h[i,:]
__global__ void init_agg_kernel(const float* __restrict__ h, int hstride,
                                const float* __restrict__ ceps, int layer,
                                float* __restrict__ agg) {
    int t = blockIdx.x * blockDim.x + threadIdx.x;   // one float4 per thread
    int row = t >> 5;
    int q = t & 31;
    if (row >= N_NODES) return;
    float c = 1.f + ceps[layer];
    float4 v = *(const float4*)(h + (size_t)row * hstride + q * 4);
    v.x *= c; v.y *= c; v.z *= c; v.w *= c;
    *(float4*)(agg + (size_t)row * HID + q * 4) = v;
}

// agg[dst,:] += h[src,:]  (warp per edge, lane = one float4 of the 128-float row)
__global__ void scatter_add_kernel(const int* __restrict__ ei,
                                   const float* __restrict__ h, int hstride,
                                   float* __restrict__ agg) {
    int warp = (blockIdx.x * blockDim.x + threadIdx.x) >> 5;
    int lane = threadIdx.x & 31;
    if (warp >= N_EDGES) return;
    int src = __ldg(&ei[warp]);
    int dst = __ldg(&ei[N_EDGES + warp]);
    float4 v = __ldg((const float4*)(h + (size_t)src * hstride + lane * 4));
    float* p = agg + (size_t)dst * HID + lane * 4;
    asm volatile("red.global.add.v4.f32 [%0], {%1,%2,%3,%4};"
                 :: "l"(p), "f"(v.x), "f"(v.y), "f"(v.z), "f"(v.w) : "memory");
}

// -------------------------- 128x128x16 tiled SGEMM ---------------------------
// C[M,N] = act(A[M,K] @ B[K,N] + bias), row-major, N % 128 == 0, K % 16 == 0
__global__ __launch_bounds__(256, 2)
void sgemm_kernel(const float* __restrict__ A, int lda,
                  const float* __restrict__ B, int ldb,
                  const float* __restrict__ bias,
                  float* __restrict__ C, int ldc,
                  int M, int N, int K, int relu) {
    const int BM = 128, BN = 128, BK = 16;
    __shared__ float As[BK][BM];
    __shared__ float Bs[BK][BN];
    int tid = threadIdx.x;
    int row0 = blockIdx.y * BM;
    int col0 = blockIdx.x * BN;
    int tx = tid & 15, ty = tid >> 4;

    float acc[8][8];
#pragma unroll
    for (int i = 0; i < 8; i++)
#pragma unroll
        for (int j = 0; j < 8; j++) acc[i][j] = 0.f;

    int arow = tid >> 2;          // 0..63
    int acol = (tid & 3) << 2;    // 0,4,8,12
    int brow = tid >> 5;          // 0..7
    int bcol = (tid & 31) << 2;   // 0..124

    for (int k0 = 0; k0 < K; k0 += BK) {
#pragma unroll
        for (int i = 0; i < 2; i++) {
            int r = arow + i * 64;
            int gr = row0 + r;
            float4 v = make_float4(0.f, 0.f, 0.f, 0.f);
            if (gr < M) v = *(const float4*)(A + (size_t)gr * lda + k0 + acol);
            As[acol + 0][r] = v.x;
            As[acol + 1][r] = v.y;
            As[acol + 2][r] = v.z;
            As[acol + 3][r] = v.w;
        }
#pragma unroll
        for (int i = 0; i < 2; i++) {
            int r = brow + i * 8;
            *(float4*)(&Bs[r][bcol]) =
                *(const float4*)(B + (size_t)(k0 + r) * ldb + col0 + bcol);
        }
        __syncthreads();
#pragma unroll
        for (int k = 0; k < BK; k++) {
            float ra[8], rb[8];
#pragma unroll
            for (int i = 0; i < 8; i++) ra[i] = As[k][ty * 8 + i];
#pragma unroll
            for (int j = 0; j < 8; j++) rb[j] = Bs[k][tx * 8 + j];
#pragma unroll
            for (int i = 0; i < 8; i++)
#pragma unroll
                for (int j = 0; j < 8; j++)
                    acc[i][j] = fmaf(ra[i], rb[j], acc[i][j]);
        }
        __syncthreads();
    }

#pragma unroll
    for (int i = 0; i < 8; i++) {
        int gr = row0 + ty * 8 + i;
        if (gr >= M) continue;
#pragma unroll
        for (int j = 0; j < 8; j += 4) {
            int gc = col0 + tx * 8 + j;
            float4 v;
            v.x = acc[i][j + 0] + (bias ? bias[gc + 0] : 0.f);
            v.y = acc[i][j + 1] + (bias ? bias[gc + 1] : 0.f);
            v.z = acc[i][j + 2] + (bias ? bias[gc + 2] : 0.f);
            v.w = acc[i][j + 3] + (bias ? bias[gc + 3] : 0.f);
            if (relu) {
                v.x = fmaxf(v.x, 0.f); v.y = fmaxf(v.y, 0.f);
                v.z = fmaxf(v.z, 0.f); v.w = fmaxf(v.w, 0.f);
            }
            *(float4*)(C + (size_t)gr * ldc + gc) = v;
        }
    }
}

// ------------------------------ batch norm -----------------------------------
#define BN_ROWS 512
__global__ void bn_stats_kernel(const float* __restrict__ Z, float* __restrict__ stats) {
    int col = threadIdx.x;                 // 128 threads
    int r0 = blockIdx.x * BN_ROWS;
    int r1 = min(r0 + BN_ROWS, N_NODES);
    float s = 0.f, sq = 0.f;
    for (int r = r0; r < r1; r++) {
        float v = Z[(size_t)r * HID + col];
        s += v;
        sq = fmaf(v, v, sq);
    }
    atomicAdd(&stats[col], s);
    atomicAdd(&stats[HID + col], sq);
}

__global__ void bn_apply_kernel(const float* __restrict__ Z,
                                const float* __restrict__ stats,
                                const float* __restrict__ gamma,
                                const float* __restrict__ beta,
                                float* __restrict__ out, int ostride) {
    int idx = blockIdx.x * blockDim.x + threadIdx.x;
    if (idx >= N_NODES * HID) return;
    int row = idx / HID, col = idx - row * HID;
    float inv_n = 1.f / (float)N_NODES;
    float mu = stats[col] * inv_n;
    float var = stats[HID + col] * inv_n - mu * mu;
    float scale = rsqrtf(var + BN_EPSF) * gamma[col];
    out[(size_t)row * ostride + col] = (Z[idx] - mu) * scale + beta[col];
}

// ------------------------------- pooling -------------------------------------
#define POOL_ROWS 1024
__global__ void pool_sum_kernel(const float* __restrict__ emb,
                                const int* __restrict__ batch,
                                float* __restrict__ gsum) {
    int col = blockIdx.y * 128 + threadIdx.x;
    int r0 = blockIdx.x * POOL_ROWS;
    int r1 = min(r0 + POOL_ROWS, N_NODES);
    float acc = 0.f;
    int cur = batch[r0];
    for (int r = r0; r < r1; r++) {
        int b = batch[r];
        if (b != cur) {
            atomicAdd(&gsum[(size_t)cur * EMBW + col], acc);
            acc = 0.f; cur = b;
        }
        acc += emb[(size_t)r * EMBW + col];
    }
    atomicAdd(&gsum[(size_t)cur * EMBW + col], acc);
}

__global__ void count_kernel(const int* __restrict__ batch, float* __restrict__ cnt) {
    __shared__ int hist[N_GRAPH];
    int tid = threadIdx.x;
    if (tid < N_GRAPH) hist[tid] = 0;
    __syncthreads();
    for (int i = blockIdx.x * blockDim.x + tid; i < N_NODES; i += gridDim.x * blockDim.x)
        atomicAdd(&hist[batch[i]], 1);
    __syncthreads();
    if (tid < N_GRAPH && hist[tid]) atomicAdd(&cnt[tid], (float)hist[tid]);
}

__global__ void pool_div_kernel(float* __restrict__ gsum, const float* __restrict__ cnt) {
    int i = blockIdx.x * blockDim.x + threadIdx.x;
    if (i >= N_GRAPH * EMBW) return;
    int g = i / EMBW;
    gsum[i] = gsum[i] / fmaxf(cnt[g], 1.f);
}

// ------------------------- small MLP (classifier) -----------------------------
__global__ void small_mlp_kernel(const float* __restrict__ A,
                                 const float* __restrict__ B,
                                 const float* __restrict__ bias,
                                 float* __restrict__ C,
                                 int M, int N, int K, int relu) {
    int idx = blockIdx.x * blockDim.x + threadIdx.x;
    if (idx >= M * N) return;
    int i = idx / N, j = idx - i * N;
    float s = bias[j];
    const float* a = A + (size_t)i * K;
    for (int k = 0; k < K; k++) s = fmaf(a[k], B[(size_t)k * N + j], s);
    if (relu) s = fmaxf(s, 0.f);
    C[idx] = s;
}

__global__ void logsoftmax_kernel(const float* __restrict__ in, float* __restrict__ out) {
    int g = blockIdx.x;
    int lane = threadIdx.x;
    float v = (lane < NCLS) ? in[g * NCLS + lane] : -INFINITY;
    float m = v;
#pragma unroll
    for (int o = 16; o > 0; o >>= 1) m = fmaxf(m, __shfl_xor_sync(0xffffffffu, m, o));
    float e = (lane < NCLS) ? expf(v - m) : 0.f;
    float s = e;
#pragma unroll
    for (int o = 16; o > 0; o >>= 1) s += __shfl_xor_sync(0xffffffffu, s, o);
    if (lane < NCLS) out[g * NCLS + lane] = v - m - logf(s);
}

// --------------------------- edge predictor ----------------------------------
// u[c,:] = relu(P0[c0] + P1[c1] + b1)   (warp per candidate)
__global__ void edge_gather_kernel(const int* __restrict__ ce,
                                   const float* __restrict__ P,
                                   const float* __restrict__ b,
                                   float* __restrict__ U) {
    int warp = (blockIdx.x * blockDim.x + threadIdx.x) >> 5;
    int lane = threadIdx.x & 31;
    if (warp >= NCANDE) return;
    int c0 = __ldg(&ce[warp]);
    int c1 = __ldg(&ce[NCANDE + warp]);
    const float4* p0 = (const float4*)(P + (size_t)c0 * 512);
    const float4* p1 = (const float4*)(P + (size_t)c1 * 512 + 256);
    float4* u = (float4*)(U + (size_t)warp * 256);
#pragma unroll
    for (int i = 0; i < 2; i++) {
        int q = lane + i * 32;          // 64 float4 = 256 floats
        float4 a = __ldg(&p0[q]);
        float4 c = __ldg(&p1[q]);
        float4 bb = *(const float4*)(b + q * 4);
        float4 r;
        r.x = fmaxf(a.x + c.x + bb.x, 0.f);
        r.y = fmaxf(a.y + c.y + bb.y, 0.f);
        r.z = fmaxf(a.z + c.z + bb.z, 0.f);
        r.w = fmaxf(a.w + c.w + bb.w, 0.f);
        u[q] = r;
    }
}

// score[c] = sigmoid(dot(u2[c,:128], w) + b)   (warp per candidate)
__global__ void edge_score_kernel(const float* __restrict__ U2,
                                  const float* __restrict__ w,
                                  const float* __restrict__ b,
                                  float* __restrict__ out) {
    int warp = (blockIdx.x * blockDim.x + threadIdx.x) >> 5;
    int lane = threadIdx.x & 31;
    if (warp >= NCANDE) return;
    float4 a = __ldg((const float4*)(U2 + (size_t)warp * 128) + lane);
    float4 wv = __ldg((const float4*)w + lane);
    float s = a.x * wv.x + a.y * wv.y + a.z * wv.z + a.w * wv.w;
#pragma unroll
    for (int o = 16; o > 0; o >>= 1) s += __shfl_xor_sync(0xffffffffu, s, o);
    if (lane == 0) {
        float z = s + b[0];
        out[warp] = 1.f / (1.f + expf(-z));
    }
}

// --------------------------------- host --------------------------------------
static void* sym_addr(const void* sym) {
    void* p = nullptr;
    cudaGetSymbolAddress(&p, sym);
    return p;
}

extern "C" void kernel_launch(void* const* d_in, const int* in_sizes, int n_in,
                              void* d_out, int out_size) {
    (void)n_in; (void)out_size;
    // ---- resolve input order ----
    const float *x, *cW1, *cb1, *cW2, *cb2, *cgamma, *cbeta, *ceps;
    const float *ncW1, *ncb1, *ncW2, *ncb2, *ncW3, *ncb3, *ncW4, *ncb4;
    const float *epW1, *epb1, *epW2, *epb2, *epW3, *epb3;
    const int *edge_index, *batch, *cand;
    bool dict_order = (in_sizes[1] == 2 * N_EDGES);
    if (dict_order) {
        x          = (const float*)d_in[0];
        edge_index = (const int*)  d_in[1];
        batch      = (const int*)  d_in[2];
        cand       = (const int*)  d_in[3];
        cW1 = (const float*)d_in[4];  cb1 = (const float*)d_in[5];
        cW2 = (const float*)d_in[6];  cb2 = (const float*)d_in[7];
        cgamma = (const float*)d_in[8]; cbeta = (const float*)d_in[9];
        ceps = (const float*)d_in[10];
        ncW1 = (const float*)d_in[11]; ncb1 = (const float*)d_in[12];
        ncW2 = (const float*)d_in[13]; ncb2 = (const float*)d_in[14];
        ncW3 = (const float*)d_in[15]; ncb3 = (const float*)d_in[16];
        ncW4 = (const float*)d_in[17]; ncb4 = (const float*)d_in[18];
        epW1 = (const float*)d_in[19]; epb1 = (const float*)d_in[20];
        epW2 = (const float*)d_in[21]; epb2 = (const float*)d_in[22];
        epW3 = (const float*)d_in[23]; epb3 = (const float*)d_in[24];
    } else {
        x = (const float*)d_in[0];
        cW1 = (const float*)d_in[1];  cb1 = (const float*)d_in[2];
        cW2 = (const float*)d_in[3];  cb2 = (const float*)d_in[4];
        cgamma = (const float*)d_in[5]; cbeta = (const float*)d_in[6];
        ceps = (const float*)d_in[7];
        ncW1 = (const float*)d_in[8];  ncb1 = (const float*)d_in[9];
        ncW2 = (const float*)d_in[10]; ncb2 = (const float*)d_in[11];
        ncW3 = (const float*)d_in[12]; ncb3 = (const float*)d_in[13];
        ncW4 = (const float*)d_in[14]; ncb4 = (const float*)d_in[15];
        epW1 = (const float*)d_in[16]; epb1 = (const float*)d_in[17];
        epW2 = (const float*)d_in[18]; epb2 = (const float*)d_in[19];
        epW3 = (const float*)d_in[20]; epb3 = (const float*)d_in[21];
        edge_index = (const int*)d_in[22];
        batch      = (const int*)d_in[23];
        cand       = (const int*)d_in[24];
    }
    float* out = (float*)d_out;

    float* p_emb  = (float*)sym_addr(g_emb);
    float* p_agg  = (float*)sym_addr(g_agg);
    float* p_z1   = (float*)sym_addr(g_z1);
    float* p_z2   = (float*)sym_addr(g_z2);
    float* p_P    = (float*)sym_addr(g_P);
    float* p_u    = (float*)sym_addr(g_u);
    float* p_u2   = (float*)sym_addr(g_u2);
    float* p_st   = (float*)sym_addr(g_stats);
    float* p_gemb = (float*)sym_addr(g_gemb);
    float* p_cnt  = (float*)sym_addr(g_cnt);
    float* p_t1   = (float*)sym_addr(g_t1);
    float* p_t2   = (float*)sym_addr(g_t2);
    float* p_t3   = (float*)sym_addr(g_t3);
    float* p_lg   = (float*)sym_addr(g_logits);

    const int T = 256;
    dim3 gemmGrid128(1, (N_NODES + 127) / 128);
    dim3 gemmGrid256(2, (N_NODES + 127) / 128);

    // ================= GIN layers =================
    for (int l = 0; l < NLAY; l++) {
        const float* h = (l == 0) ? x : (p_emb + (l - 1) * HID);
        int hstride = (l == 0) ? HID : EMBW;

        init_agg_kernel<<<(N_NODES * 32 + T - 1) / T, T>>>(h, hstride, ceps, l, p_agg);
        scatter_add_kernel<<<(N_EDGES * 32 + T - 1) / T, T>>>(edge_index, h, hstride, p_agg);

        sgemm_kernel<<<gemmGrid128, 256>>>(p_agg, HID, cW1 + (size_t)l * HID * HID, HID,
                                           cb1 + l * HID, p_z1, HID,
                                           N_NODES, HID, HID, 1);
        sgemm_kernel<<<gemmGrid128, 256>>>(p_z1, HID, cW2 + (size_t)l * HID * HID, HID,
                                           cb2 + l * HID, p_z2, HID,
                                           N_NODES, HID, HID, 1);

        zero_kernel<<<1, 256>>>(p_st, 2 * HID);
        bn_stats_kernel<<<(N_NODES + BN_ROWS - 1) / BN_ROWS, HID>>>(p_z2, p_st);
        bn_apply_kernel<<<(N_NODES * HID + T - 1) / T, T>>>(
            p_z2, p_st, cgamma + l * HID, cbeta + l * HID, p_emb + l * HID, EMBW);
    }

    // ================= global mean pool =================
    zero_kernel<<<(N_GRAPH * EMBW + T - 1) / T, T>>>(p_gemb, N_GRAPH * EMBW);
    zero_kernel<<<1, 64>>>(p_cnt, N_GRAPH);
    {
        dim3 pg((N_NODES + POOL_ROWS - 1) / POOL_ROWS, EMBW / 128);
        pool_sum_kernel<<<pg, 128>>>(p_emb, batch, p_gemb);
    }
    count_kernel<<<128, 256>>>(batch, p_cnt);
    pool_div_kernel<<<(N_GRAPH * EMBW + T - 1) / T, T>>>(p_gemb, p_cnt);

    // ================= node classifier =================
    small_mlp_kernel<<<(N_GRAPH * 256 + T - 1) / T, T>>>(p_gemb, ncW1, ncb1, p_t1,
                                                         N_GRAPH, 256, EMBW, 1);
    small_mlp_kernel<<<(N_GRAPH * 128 + T - 1) / T, T>>>(p_t1, ncW2, ncb2, p_t2,
                                                         N_GRAPH, 128, 256, 1);
    small_mlp_kernel<<<(N_GRAPH * 128 + T - 1) / T, T>>>(p_t2, ncW3, ncb3, p_t3,
                                                         N_GRAPH, 128, 128, 1);
    small_mlp_kernel<<<(N_GRAPH * NCLS + T - 1) / T, T>>>(p_t3, ncW4, ncb4, p_lg,
                                                          N_GRAPH, NCLS, 128, 0);
    logsoftmax_kernel<<<N_GRAPH, 32>>>(p_lg, out);   // out[0 : 64*16)

    // ================= edge predictor =================
    // P0 = emb @ epW1[0:512,:]  ;  P1 = emb @ epW1[512:1024,:]
    sgemm_kernel<<<gemmGrid256, 256>>>(p_emb, EMBW, epW1, 256, nullptr,
                                       p_P, 512, N_NODES, 256, EMBW, 0);
    sgemm_kernel<<<gemmGrid256, 256>>>(p_emb, EMBW, epW1 + (size_t)512 * 256, 256, nullptr,
                                       p_P + 256, 512, N_NODES, 256, EMBW, 0);
    edge_gather_kernel<<<(NCANDE * 32 + T - 1) / T, T>>>(cand, p_P, epb1, p_u);
    sgemm_kernel<<<gemmGrid128, 256>>>(p_u, 256, epW2, 128, epb2, p_u2, 128,
                                       NCANDE, 128, 256, 1);
    edge_score_kernel<<<(NCANDE * 32 + T - 1) / T, T>>>(p_u2, epW3, epb3,
                                                        out + N_GRAPH * NCLS);
}

// round 2
// speedup vs baseline: 1.6081x; 1.6081x over previous
#include <cuda_runtime.h>
#include <math.h>
#include <stdint.h>

#define N_NODES 100000
#define N_EDGES 1600000
#define N_GRAPH 64
#define HID     128
#define NLAY    4
#define NCLS    16
#define NCANDE  100000
#define EMBW    512           // NLAY*HID
#define BN_EPSF 1e-5f

// ------------------------- persistent device scratch -------------------------
__device__ float g_emb[(size_t)N_NODES * EMBW];   // per-layer BN outputs, concatenated
__device__ float g_agg[(size_t)N_NODES * HID];
__device__ float g_z1 [(size_t)N_NODES * HID];
__device__ float g_z2 [(size_t)N_NODES * HID];
__device__ float g_P  [(size_t)NCANDE * 512];     // [P0 | P1]
__device__ float g_u  [(size_t)NCANDE * 256];
__device__ float g_u2 [(size_t)NCANDE * 128];
__device__ float g_stats[2 * HID];                // col sums, col sumsq
__device__ float g_gemb[N_GRAPH * EMBW];
__device__ float g_cnt [N_GRAPH];
__device__ float g_t1[N_GRAPH * 256];
__device__ float g_t2[N_GRAPH * 128];
__device__ float g_t3[N_GRAPH * 128];
__device__ float g_logits[N_GRAPH * NCLS];

// ------------------------------- small utils --------------------------------
__global__ void zero_kernel(float* p, int n) {
    int i = blockIdx.x * blockDim.x + threadIdx.x;
    if (i < n) p[i] = 0.f;
}

// agg[i,:] = (1+eps[l]) * h[i,:]
__global__ void init_agg_kernel(const float* __restrict__ h, int hstride,
                                const float* __restrict__ ceps, int layer,
                                float* __restrict__ agg) {
    int t = blockIdx.x * blockDim.x + threadIdx.x;   // one float4 per thread
    int row = t >> 5;
    int q = t & 31;
    if (row >= N_NODES) return;
    float c = 1.f + ceps[layer];
    float4 v = *(const float4*)(h + (size_t)row * hstride + q * 4);
    v.x *= c; v.y *= c; v.z *= c; v.w *= c;
    *(float4*)(agg + (size_t)row * HID + q * 4) = v;
}

// agg[dst,:] += h[src,:]  (warp per edge, lane = one float4 of the 128-float row)
__global__ void scatter_add_kernel(const int* __restrict__ ei,
                                   const float* __restrict__ h, int hstride,
                                   float* __restrict__ agg) {
    int warp = (blockIdx.x * blockDim.x + threadIdx.x) >> 5;
    int lane = threadIdx.x & 31;
    if (warp >= N_EDGES) return;
    int src = __ldg(&ei[warp]);
    int dst = __ldg(&ei[N_EDGES + warp]);
    float4 v = __ldg((const float4*)(h + (size_t)src * hstride + lane * 4));
    float* p = agg + (size_t)dst * HID + lane * 4;
    asm volatile("red.global.add.v4.f32 [%0], {%1,%2,%3,%4};"
                 :: "l"(p), "f"(v.x), "f"(v.y), "f"(v.z), "f"(v.w) : "memory");
}

// ----------------------- TF32 tensor-core GEMM -------------------------------
// C[M,N] = act(A[M,K] @ B[K,N] + bias), row-major. N % 128 == 0, K % 32 == 0.
// CTA tile 128x128x32, 8 warps, warp tile 64x32, mma.m16n8k8.tf32.

__device__ __forceinline__ unsigned f2tf32(float f) {
    unsigned r;
    asm("cvt.rna.tf32.f32 %0, %1;" : "=r"(r) : "f"(f));
    return r;
}

#define SA 36     // As row stride (words): frag banks = 4*gid+tig = lane (conflict-free)
#define SB 136    // Bs row stride (words): frag banks = 8*tig+gid (conflict-free)

__global__ __launch_bounds__(256, 2)
void tf32_gemm_kernel(const float* __restrict__ A, int lda,
                      const float* __restrict__ B, int ldb,
                      const float* __restrict__ bias,
                      float* __restrict__ C, int ldc,
                      int M, int N, int K, int relu) {
    __shared__ unsigned As[128 * SA];   // [m][k] layout
    __shared__ unsigned Bs[32 * SB];    // [k][n] layout
    int tid = threadIdx.x;
    int warp = tid >> 5, lane = tid & 31;
    int gid = lane >> 2, tig = lane & 3;
    int row0 = blockIdx.y * 128;
    int col0 = blockIdx.x * 128;
    int warpM = (warp >> 2) * 64;
    int warpN = (warp & 3) * 32;

    float acc[4][4][4];
#pragma unroll
    for (int a = 0; a < 4; a++)
#pragma unroll
        for (int b = 0; b < 4; b++)
#pragma unroll
            for (int c = 0; c < 4; c++) acc[a][b][c] = 0.f;

    for (int k0 = 0; k0 < K; k0 += 32) {
        // stage A tile 128x32 (coalesced: 8 threads cover a 128B row-chunk)
#pragma unroll
        for (int i = 0; i < 4; i++) {
            int f = tid + i * 256;
            int r = f >> 3, cq = (f & 7) << 2;
            float4 v = make_float4(0.f, 0.f, 0.f, 0.f);
            if (row0 + r < M) v = *(const float4*)(A + (size_t)(row0 + r) * lda + k0 + cq);
            uint4 w;
            w.x = f2tf32(v.x); w.y = f2tf32(v.y); w.z = f2tf32(v.z); w.w = f2tf32(v.w);
            *(uint4*)(As + r * SA + cq) = w;
        }
        // stage B tile 32x128 (coalesced: 32 threads cover a full 512B row)
#pragma unroll
        for (int i = 0; i < 4; i++) {
            int f = tid + i * 256;
            int r = f >> 5, cq = (f & 31) << 2;
            float4 v = *(const float4*)(B + (size_t)(k0 + r) * ldb + col0 + cq);
            uint4 w;
            w.x = f2tf32(v.x); w.y = f2tf32(v.y); w.z = f2tf32(v.z); w.w = f2tf32(v.w);
            *(uint4*)(Bs + r * SB + cq) = w;
        }
        __syncthreads();

#pragma unroll
        for (int ks = 0; ks < 32; ks += 8) {
            unsigned af[4][4], bf[4][2];
#pragma unroll
            for (int mt = 0; mt < 4; mt++) {
                const unsigned* p = As + (warpM + mt * 16 + gid) * SA + ks + tig;
                af[mt][0] = p[0];
                af[mt][1] = p[8 * SA];
                af[mt][2] = p[4];
                af[mt][3] = p[8 * SA + 4];
            }
#pragma unroll
            for (int nt = 0; nt < 4; nt++) {
                const unsigned* p = Bs + (ks + tig) * SB + warpN + nt * 8 + gid;
                bf[nt][0] = p[0];
                bf[nt][1] = p[4 * SB];
            }
#pragma unroll
            for (int mt = 0; mt < 4; mt++)
#pragma unroll
                for (int nt = 0; nt < 4; nt++) {
                    asm volatile(
                        "mma.sync.aligned.m16n8k8.row.col.f32.tf32.tf32.f32 "
                        "{%0,%1,%2,%3}, {%4,%5,%6,%7}, {%8,%9}, {%0,%1,%2,%3};"
                        : "+f"(acc[mt][nt][0]), "+f"(acc[mt][nt][1]),
                          "+f"(acc[mt][nt][2]), "+f"(acc[mt][nt][3])
                        : "r"(af[mt][0]), "r"(af[mt][1]), "r"(af[mt][2]), "r"(af[mt][3]),
                          "r"(bf[nt][0]), "r"(bf[nt][1]));
                }
        }
        __syncthreads();
    }

    // epilogue: c0/c1 at (gid, 2*tig(+1)), c2/c3 at (gid+8, 2*tig(+1))
#pragma unroll
    for (int mt = 0; mt < 4; mt++) {
#pragma unroll
        for (int half = 0; half < 2; half++) {
            int gr = row0 + warpM + mt * 16 + gid + half * 8;
            if (gr >= M) continue;
#pragma unroll
            for (int nt = 0; nt < 4; nt++) {
                int gc = col0 + warpN + nt * 8 + tig * 2;
                float2 v;
                v.x = acc[mt][nt][half * 2 + 0] + (bias ? bias[gc + 0] : 0.f);
                v.y = acc[mt][nt][half * 2 + 1] + (bias ? bias[gc + 1] : 0.f);
                if (relu) { v.x = fmaxf(v.x, 0.f); v.y = fmaxf(v.y, 0.f); }
                *(float2*)(C + (size_t)gr * ldc + gc) = v;
            }
        }
    }
}

// ------------------------------ batch norm -----------------------------------
#define BN_ROWS 512
__global__ void bn_stats_kernel(const float* __restrict__ Z, float* __restrict__ stats) {
    int col = threadIdx.x;                 // 128 threads
    int r0 = blockIdx.x * BN_ROWS;
    int r1 = min(r0 + BN_ROWS, N_NODES);
    float s = 0.f, sq = 0.f;
    for (int r = r0; r < r1; r++) {
        float v = Z[(size_t)r * HID + col];
        s += v;
        sq = fmaf(v, v, sq);
    }
    atomicAdd(&stats[col], s);
    atomicAdd(&stats[HID + col], sq);
}

__global__ void bn_apply_kernel(const float* __restrict__ Z,
                                const float* __restrict__ stats,
                                const float* __restrict__ gamma,
                                const float* __restrict__ beta,
                                float* __restrict__ out, int ostride) {
    int idx = blockIdx.x * blockDim.x + threadIdx.x;
    if (idx >= N_NODES * HID) return;
    int row = idx / HID, col = idx - row * HID;
    float inv_n = 1.f / (float)N_NODES;
    float mu = stats[col] * inv_n;
    float var = stats[HID + col] * inv_n - mu * mu;
    float scale = rsqrtf(var + BN_EPSF) * gamma[col];
    out[(size_t)row * ostride + col] = (Z[idx] - mu) * scale + beta[col];
}

// ------------------------------- pooling -------------------------------------
#define POOL_ROWS 1024
__global__ void pool_sum_kernel(const float* __restrict__ emb,
                                const int* __restrict__ batch,
                                float* __restrict__ gsum) {
    int col = blockIdx.y * 128 + threadIdx.x;
    int r0 = blockIdx.x * POOL_ROWS;
    int r1 = min(r0 + POOL_ROWS, N_NODES);
    float acc = 0.f;
    int cur = batch[r0];
    for (int r = r0; r < r1; r++) {
        int b = batch[r];
        if (b != cur) {
            atomicAdd(&gsum[(size_t)cur * EMBW + col], acc);
            acc = 0.f; cur = b;
        }
        acc += emb[(size_t)r * EMBW + col];
    }
    atomicAdd(&gsum[(size_t)cur * EMBW + col], acc);
}

__global__ void count_kernel(const int* __restrict__ batch, float* __restrict__ cnt) {
    __shared__ int hist[N_GRAPH];
    int tid = threadIdx.x;
    if (tid < N_GRAPH) hist[tid] = 0;
    __syncthreads();
    for (int i = blockIdx.x * blockDim.x + tid; i < N_NODES; i += gridDim.x * blockDim.x)
        atomicAdd(&hist[batch[i]], 1);
    __syncthreads();
    if (tid < N_GRAPH && hist[tid]) atomicAdd(&cnt[tid], (float)hist[tid]);
}

__global__ void pool_div_kernel(float* __restrict__ gsum, const float* __restrict__ cnt) {
    int i = blockIdx.x * blockDim.x + threadIdx.x;
    if (i >= N_GRAPH * EMBW) return;
    int g = i / EMBW;
    gsum[i] = gsum[i] / fmaxf(cnt[g], 1.f);
}

// ------------------------- small MLP (classifier) -----------------------------
__global__ void small_mlp_kernel(const float* __restrict__ A,
                                 const float* __restrict__ B,
                                 const float* __restrict__ bias,
                                 float* __restrict__ C,
                                 int M, int N, int K, int relu) {
    int idx = blockIdx.x * blockDim.x + threadIdx.x;
    if (idx >= M * N) return;
    int i = idx / N, j = idx - i * N;
    float s = bias[j];
    const float* a = A + (size_t)i * K;
    for (int k = 0; k < K; k++) s = fmaf(a[k], B[(size_t)k * N + j], s);
    if (relu) s = fmaxf(s, 0.f);
    C[idx] = s;
}

__global__ void logsoftmax_kernel(const float* __restrict__ in, float* __restrict__ out) {
    int g = blockIdx.x;
    int lane = threadIdx.x;
    float v = (lane < NCLS) ? in[g * NCLS + lane] : -INFINITY;
    float m = v;
#pragma unroll
    for (int o = 16; o > 0; o >>= 1) m = fmaxf(m, __shfl_xor_sync(0xffffffffu, m, o));
    float e = (lane < NCLS) ? expf(v - m) : 0.f;
    float s = e;
#pragma unroll
    for (int o = 16; o > 0; o >>= 1) s += __shfl_xor_sync(0xffffffffu, s, o);
    if (lane < NCLS) out[g * NCLS + lane] = v - m - logf(s);
}

// --------------------------- edge predictor ----------------------------------
// u[c,:] = relu(P0[c0] + P1[c1] + b1)   (warp per candidate)
__global__ void edge_gather_kernel(const int* __restrict__ ce,
                                   const float* __restrict__ P,
                                   const float* __restrict__ b,
                                   float* __restrict__ U) {
    int warp = (blockIdx.x * blockDim.x + threadIdx.x) >> 5;
    int lane = threadIdx.x & 31;
    if (warp >= NCANDE) return;
    int c0 = __ldg(&ce[warp]);
    int c1 = __ldg(&ce[NCANDE + warp]);
    const float4* p0 = (const float4*)(P + (size_t)c0 * 512);
    const float4* p1 = (const float4*)(P + (size_t)c1 * 512 + 256);
    float4* u = (float4*)(U + (size_t)warp * 256);
#pragma unroll
    for (int i = 0; i < 2; i++) {
        int q = lane + i * 32;          // 64 float4 = 256 floats
        float4 a = __ldg(&p0[q]);
        float4 c = __ldg(&p1[q]);
        float4 bb = *(const float4*)(b + q * 4);
        float4 r;
        r.x = fmaxf(a.x + c.x + bb.x, 0.f);
        r.y = fmaxf(a.y + c.y + bb.y, 0.f);
        r.z = fmaxf(a.z + c.z + bb.z, 0.f);
        r.w = fmaxf(a.w + c.w + bb.w, 0.f);
        u[q] = r;
    }
}

// score[c] = sigmoid(dot(u2[c,:128], w) + b)   (warp per candidate)
__global__ void edge_score_kernel(const float* __restrict__ U2,
                                  const float* __restrict__ w,
                                  const float* __restrict__ b,
                                  float* __restrict__ out) {
    int warp = (blockIdx.x * blockDim.x + threadIdx.x) >> 5;
    int lane = threadIdx.x & 31;
    if (warp >= NCANDE) return;
    float4 a = __ldg((const float4*)(U2 + (size_t)warp * 128) + lane);
    float4 wv = __ldg((const float4*)w + lane);
    float s = a.x * wv.x + a.y * wv.y + a.z * wv.z + a.w * wv.w;
#pragma unroll
    for (int o = 16; o > 0; o >>= 1) s += __shfl_xor_sync(0xffffffffu, s, o);
    if (lane == 0) {
        float z = s + b[0];
        out[warp] = 1.f / (1.f + expf(-z));
    }
}

// --------------------------------- host --------------------------------------
static void* sym_addr(const void* sym) {
    void* p = nullptr;
    cudaGetSymbolAddress(&p, sym);
    return p;
}

extern "C" void kernel_launch(void* const* d_in, const int* in_sizes, int n_in,
                              void* d_out, int out_size) {
    (void)n_in; (void)out_size;
    // ---- resolve input order ----
    const float *x, *cW1, *cb1, *cW2, *cb2, *cgamma, *cbeta, *ceps;
    const float *ncW1, *ncb1, *ncW2, *ncb2, *ncW3, *ncb3, *ncW4, *ncb4;
    const float *epW1, *epb1, *epW2, *epb2, *epW3, *epb3;
    const int *edge_index, *batch, *cand;
    bool dict_order = (in_sizes[1] == 2 * N_EDGES);
    if (dict_order) {
        x          = (const float*)d_in[0];
        edge_index = (const int*)  d_in[1];
        batch      = (const int*)  d_in[2];
        cand       = (const int*)  d_in[3];
        cW1 = (const float*)d_in[4];  cb1 = (const float*)d_in[5];
        cW2 = (const float*)d_in[6];  cb2 = (const float*)d_in[7];
        cgamma = (const float*)d_in[8]; cbeta = (const float*)d_in[9];
        ceps = (const float*)d_in[10];
        ncW1 = (const float*)d_in[11]; ncb1 = (const float*)d_in[12];
        ncW2 = (const float*)d_in[13]; ncb2 = (const float*)d_in[14];
        ncW3 = (const float*)d_in[15]; ncb3 = (const float*)d_in[16];
        ncW4 = (const float*)d_in[17]; ncb4 = (const float*)d_in[18];
        epW1 = (const float*)d_in[19]; epb1 = (const float*)d_in[20];
        epW2 = (const float*)d_in[21]; epb2 = (const float*)d_in[22];
        epW3 = (const float*)d_in[23]; epb3 = (const float*)d_in[24];
    } else {
        x = (const float*)d_in[0];
        cW1 = (const float*)d_in[1];  cb1 = (const float*)d_in[2];
        cW2 = (const float*)d_in[3];  cb2 = (const float*)d_in[4];
        cgamma = (const float*)d_in[5]; cbeta = (const float*)d_in[6];
        ceps = (const float*)d_in[7];
        ncW1 = (const float*)d_in[8];  ncb1 = (const float*)d_in[9];
        ncW2 = (const float*)d_in[10]; ncb2 = (const float*)d_in[11];
        ncW3 = (const float*)d_in[12]; ncb3 = (const float*)d_in[13];
        ncW4 = (const float*)d_in[14]; ncb4 = (const float*)d_in[15];
        epW1 = (const float*)d_in[16]; epb1 = (const float*)d_in[17];
        epW2 = (const float*)d_in[18]; epb2 = (const float*)d_in[19];
        epW3 = (const float*)d_in[20]; epb3 = (const float*)d_in[21];
        edge_index = (const int*)d_in[22];
        batch      = (const int*)d_in[23];
        cand       = (const int*)d_in[24];
    }
    float* out = (float*)d_out;

    float* p_emb  = (float*)sym_addr(g_emb);
    float* p_agg  = (float*)sym_addr(g_agg);
    float* p_z1   = (float*)sym_addr(g_z1);
    float* p_z2   = (float*)sym_addr(g_z2);
    float* p_P    = (float*)sym_addr(g_P);
    float* p_u    = (float*)sym_addr(g_u);
    float* p_u2   = (float*)sym_addr(g_u2);
    float* p_st   = (float*)sym_addr(g_stats);
    float* p_gemb = (float*)sym_addr(g_gemb);
    float* p_cnt  = (float*)sym_addr(g_cnt);
    float* p_t1   = (float*)sym_addr(g_t1);
    float* p_t2   = (float*)sym_addr(g_t2);
    float* p_t3   = (float*)sym_addr(g_t3);
    float* p_lg   = (float*)sym_addr(g_logits);

    const int T = 256;
    dim3 gemmGrid128(1, (N_NODES + 127) / 128);
    dim3 gemmGrid256(2, (N_NODES + 127) / 128);

    // ================= GIN layers =================
    for (int l = 0; l < NLAY; l++) {
        const float* h = (l == 0) ? x : (p_emb + (l - 1) * HID);
        int hstride = (l == 0) ? HID : EMBW;

        init_agg_kernel<<<(N_NODES * 32 + T - 1) / T, T>>>(h, hstride, ceps, l, p_agg);
        scatter_add_kernel<<<(N_EDGES * 32 + T - 1) / T, T>>>(edge_index, h, hstride, p_agg);

        tf32_gemm_kernel<<<gemmGrid128, 256>>>(p_agg, HID, cW1 + (size_t)l * HID * HID, HID,
                                               cb1 + l * HID, p_z1, HID,
                                               N_NODES, HID, HID, 1);
        tf32_gemm_kernel<<<gemmGrid128, 256>>>(p_z1, HID, cW2 + (size_t)l * HID * HID, HID,
                                               cb2 + l * HID, p_z2, HID,
                                               N_NODES, HID, HID, 1);

        zero_kernel<<<1, 256>>>(p_st, 2 * HID);
        bn_stats_kernel<<<(N_NODES + BN_ROWS - 1) / BN_ROWS, HID>>>(p_z2, p_st);
        bn_apply_kernel<<<(N_NODES * HID + T - 1) / T, T>>>(
            p_z2, p_st, cgamma + l * HID, cbeta + l * HID, p_emb + l * HID, EMBW);
    }

    // ================= global mean pool =================
    zero_kernel<<<(N_GRAPH * EMBW + T - 1) / T, T>>>(p_gemb, N_GRAPH * EMBW);
    zero_kernel<<<1, 64>>>(p_cnt, N_GRAPH);
    {
        dim3 pg((N_NODES + POOL_ROWS - 1) / POOL_ROWS, EMBW / 128);
        pool_sum_kernel<<<pg, 128>>>(p_emb, batch, p_gemb);
    }
    count_kernel<<<128, 256>>>(batch, p_cnt);
    pool_div_kernel<<<(N_GRAPH * EMBW + T - 1) / T, T>>>(p_gemb, p_cnt);

    // ================= node classifier =================
    small_mlp_kernel<<<(N_GRAPH * 256 + T - 1) / T, T>>>(p_gemb, ncW1, ncb1, p_t1,
                                                         N_GRAPH, 256, EMBW, 1);
    small_mlp_kernel<<<(N_GRAPH * 128 + T - 1) / T, T>>>(p_t1, ncW2, ncb2, p_t2,
                                                         N_GRAPH, 128, 256, 1);
    small_mlp_kernel<<<(N_GRAPH * 128 + T - 1) / T, T>>>(p_t2, ncW3, ncb3, p_t3,
                                                         N_GRAPH, 128, 128, 1);
    small_mlp_kernel<<<(N_GRAPH * NCLS + T - 1) / T, T>>>(p_t3, ncW4, ncb4, p_lg,
                                                          N_GRAPH, NCLS, 128, 0);
    logsoftmax_kernel<<<N_GRAPH, 32>>>(p_lg, out);   // out[0 : 64*16)

    // ================= edge predictor =================
    // P0 = emb @ epW1[0:512,:]  ;  P1 = emb @ epW1[512:1024,:]
    tf32_gemm_kernel<<<gemmGrid256, 256>>>(p_emb, EMBW, epW1, 256, nullptr,
                                           p_P, 512, N_NODES, 256, EMBW, 0);
    tf32_gemm_kernel<<<gemmGrid256, 256>>>(p_emb, EMBW, epW1 + (size_t)512 * 256, 256, nullptr,
                                           p_P + 256, 512, N_NODES, 256, EMBW, 0);
    edge_gather_kernel<<<(NCANDE * 32 + T - 1) / T, T>>>(cand, p_P, epb1, p_u);
    tf32_gemm_kernel<<<gemmGrid128, 256>>>(p_u, 256, epW2, 128, epb2, p_u2, 128,
                                           NCANDE, 128, 256, 1);
    edge_score_kernel<<<(NCANDE * 32 + T - 1) / T, T>>>(p_u2, epW3, epb3,
                                                        out + N_GRAPH * NCLS);
}

// round 3
// speedup vs baseline: 2.1424x; 1.3323x over previous
#include <cuda_runtime.h>
#include <math.h>
#include <stdint.h>

#define N_NODES 100000
#define N_EDGES 1600000
#define N_GRAPH 64
#define HID     128
#define NLAY    4
#define NCLS    16
#define NCANDE  100000
#define EMBW    512           // NLAY*HID
#define BN_EPSF 1e-5f

// ------------------------- persistent device scratch -------------------------
__device__ float g_emb[(size_t)N_NODES * EMBW];
__device__ float g_agg[(size_t)N_NODES * HID];
__device__ float g_z1 [(size_t)N_NODES * HID];
__device__ float g_z2 [(size_t)N_NODES * HID];
__device__ float g_P  [(size_t)NCANDE * 512];
__device__ float g_u  [(size_t)NCANDE * 256];
__device__ float g_u2 [(size_t)NCANDE * 128];
__device__ float g_stats[2 * HID];
__device__ float g_gemb[N_GRAPH * EMBW];
__device__ float g_cnt [N_GRAPH];
__device__ float g_t1[N_GRAPH * 256];
__device__ float g_t2[N_GRAPH * 128];
__device__ float g_t3[N_GRAPH * 128];
__device__ float g_logits[N_GRAPH * NCLS];
// CSR scratch
__device__ int g_deg[N_NODES];
__device__ int g_off[N_NODES + 1];
__device__ int g_pos[N_NODES];
__device__ int g_csr[N_EDGES];
__device__ int g_bsum[128];

// ------------------------------- small utils --------------------------------
__global__ void zero_kernel(float* p, int n) {
    int i = blockIdx.x * blockDim.x + threadIdx.x;
    if (i < n) p[i] = 0.f;
}
__global__ void zeroi_kernel(int* p, int n) {
    int i = blockIdx.x * blockDim.x + threadIdx.x;
    if (i < n) p[i] = 0;
}

// ------------------------------ CSR build ------------------------------------
__global__ void hist_kernel(const int* __restrict__ ei, int* __restrict__ deg) {
    int e = blockIdx.x * blockDim.x + threadIdx.x;
    if (e < N_EDGES) atomicAdd(&deg[ei[N_EDGES + e]], 1);
}

#define SCAN_B 1024
__global__ void scan_block_kernel(const int* __restrict__ deg, int* __restrict__ off,
                                  int* __restrict__ bsum, int n) {
    __shared__ int sh[SCAN_B];
    int g = blockIdx.x * SCAN_B + threadIdx.x;
    int v = (g < n) ? deg[g] : 0;
    sh[threadIdx.x] = v;
    __syncthreads();
#pragma unroll
    for (int o = 1; o < SCAN_B; o <<= 1) {
        int t = (threadIdx.x >= o) ? sh[threadIdx.x - o] : 0;
        __syncthreads();
        sh[threadIdx.x] += t;
        __syncthreads();
    }
    if (g < n) off[g] = sh[threadIdx.x] - v;            // exclusive
    if (threadIdx.x == SCAN_B - 1) bsum[blockIdx.x] = sh[SCAN_B - 1];
}

__global__ void scan_bsum_kernel(int* __restrict__ bsum, int nb) {
    __shared__ int sh[128];
    int v = (threadIdx.x < nb) ? bsum[threadIdx.x] : 0;
    sh[threadIdx.x] = v;
    __syncthreads();
#pragma unroll
    for (int o = 1; o < 128; o <<= 1) {
        int t = (threadIdx.x >= o) ? sh[threadIdx.x - o] : 0;
        __syncthreads();
        sh[threadIdx.x] += t;
        __syncthreads();
    }
    if (threadIdx.x < nb) bsum[threadIdx.x] = sh[threadIdx.x] - v;  // exclusive
}

__global__ void scan_add_kernel(int* __restrict__ off, const int* __restrict__ bsum,
                                int* __restrict__ pos, int n) {
    int g = blockIdx.x * blockDim.x + threadIdx.x;
    if (g < n) {
        int o = off[g] + bsum[g / SCAN_B];
        off[g] = o;
        pos[g] = o;
    }
    if (g == n) off[n] = N_EDGES;
}

__global__ void csr_fill_kernel(const int* __restrict__ ei, int* __restrict__ pos,
                                int* __restrict__ csr) {
    int e = blockIdx.x * blockDim.x + threadIdx.x;
    if (e >= N_EDGES) return;
    int dst = ei[N_EDGES + e];
    int p = atomicAdd(&pos[dst], 1);
    csr[p] = ei[e];
}

// ------------------- GIN aggregation: warp-per-node gather --------------------
// agg[i,:] = (1+eps)*h[i,:] + sum_{j in N(i)} h[j,:]
__global__ void gin_gather_kernel(const int* __restrict__ off,
                                  const int* __restrict__ csr,
                                  const float* __restrict__ h, int hstride,
                                  const float* __restrict__ ceps, int layer,
                                  float* __restrict__ agg) {
    int node = (blockIdx.x * blockDim.x + threadIdx.x) >> 5;
    int lane = threadIdx.x & 31;
    if (node >= N_NODES) return;
    int s = off[node], e = off[node + 1];
    float c = 1.f + __ldg(&ceps[layer]);
    float4 acc = __ldg((const float4*)(h + (size_t)node * hstride) + lane);
    acc.x *= c; acc.y *= c; acc.z *= c; acc.w *= c;
    for (int i = s; i < e; i++) {
        int src = __ldg(&csr[i]);
        float4 v = __ldg((const float4*)(h + (size_t)src * hstride) + lane);
        acc.x += v.x; acc.y += v.y; acc.z += v.z; acc.w += v.w;
    }
    *((float4*)(agg + (size_t)node * HID) + lane) = acc;
}

// ----------------------- TF32 tensor-core GEMM -------------------------------
__device__ __forceinline__ unsigned f2tf32(float f) {
    unsigned r;
    asm("cvt.rna.tf32.f32 %0, %1;" : "=r"(r) : "f"(f));
    return r;
}

#define SA 36
#define SB 136

__global__ __launch_bounds__(256, 2)
void tf32_gemm_kernel(const float* __restrict__ A, int lda,
                      const float* __restrict__ B, int ldb,
                      const float* __restrict__ bias,
                      float* __restrict__ C, int ldc,
                      int M, int N, int K, int relu) {
    __shared__ unsigned As[128 * SA];   // [m][k]
    __shared__ unsigned Bs[32 * SB];    // [k][n]
    int tid = threadIdx.x;
    int warp = tid >> 5, lane = tid & 31;
    int gid = lane >> 2, tig = lane & 3;
    int row0 = blockIdx.y * 128;
    int col0 = blockIdx.x * 128;
    int warpM = (warp >> 2) * 64;
    int warpN = (warp & 3) * 32;

    float acc[4][4][4];
#pragma unroll
    for (int a = 0; a < 4; a++)
#pragma unroll
        for (int b = 0; b < 4; b++)
#pragma unroll
            for (int c = 0; c < 4; c++) acc[a][b][c] = 0.f;

    for (int k0 = 0; k0 < K; k0 += 32) {
#pragma unroll
        for (int i = 0; i < 4; i++) {
            int f = tid + i * 256;
            int r = f >> 3, cq = (f & 7) << 2;
            float4 v = make_float4(0.f, 0.f, 0.f, 0.f);
            if (row0 + r < M) v = *(const float4*)(A + (size_t)(row0 + r) * lda + k0 + cq);
            uint4 w;
            w.x = f2tf32(v.x); w.y = f2tf32(v.y); w.z = f2tf32(v.z); w.w = f2tf32(v.w);
            *(uint4*)(As + r * SA + cq) = w;
        }
#pragma unroll
        for (int i = 0; i < 4; i++) {
            int f = tid + i * 256;
            int r = f >> 5, cq = (f & 31) << 2;
            float4 v = *(const float4*)(B + (size_t)(k0 + r) * ldb + col0 + cq);
            uint4 w;
            w.x = f2tf32(v.x); w.y = f2tf32(v.y); w.z = f2tf32(v.z); w.w = f2tf32(v.w);
            *(uint4*)(Bs + r * SB + cq) = w;
        }
        __syncthreads();

#pragma unroll
        for (int ks = 0; ks < 32; ks += 8) {
            unsigned af[4][4], bf[4][2];
#pragma unroll
            for (int mt = 0; mt < 4; mt++) {
                const unsigned* p = As + (warpM + mt * 16 + gid) * SA + ks + tig;
                af[mt][0] = p[0];
                af[mt][1] = p[8 * SA];
                af[mt][2] = p[4];
                af[mt][3] = p[8 * SA + 4];
            }
#pragma unroll
            for (int nt = 0; nt < 4; nt++) {
                const unsigned* p = Bs + (ks + tig) * SB + warpN + nt * 8 + gid;
                bf[nt][0] = p[0];
                bf[nt][1] = p[4 * SB];
            }
#pragma unroll
            for (int mt = 0; mt < 4; mt++)
#pragma unroll
                for (int nt = 0; nt < 4; nt++) {
                    asm volatile(
                        "mma.sync.aligned.m16n8k8.row.col.f32.tf32.tf32.f32 "
                        "{%0,%1,%2,%3}, {%4,%5,%6,%7}, {%8,%9}, {%0,%1,%2,%3};"
                        : "+f"(acc[mt][nt][0]), "+f"(acc[mt][nt][1]),
                          "+f"(acc[mt][nt][2]), "+f"(acc[mt][nt][3])
                        : "r"(af[mt][0]), "r"(af[mt][1]), "r"(af[mt][2]), "r"(af[mt][3]),
                          "r"(bf[nt][0]), "r"(bf[nt][1]));
                }
        }
        __syncthreads();
    }

#pragma unroll
    for (int mt = 0; mt < 4; mt++) {
#pragma unroll
        for (int half = 0; half < 2; half++) {
            int gr = row0 + warpM + mt * 16 + gid + half * 8;
            if (gr >= M) continue;
#pragma unroll
            for (int nt = 0; nt < 4; nt++) {
                int gc = col0 + warpN + nt * 8 + tig * 2;
                float2 v;
                v.x = acc[mt][nt][half * 2 + 0] + (bias ? bias[gc + 0] : 0.f);
                v.y = acc[mt][nt][half * 2 + 1] + (bias ? bias[gc + 1] : 0.f);
                if (relu) { v.x = fmaxf(v.x, 0.f); v.y = fmaxf(v.y, 0.f); }
                *(float2*)(C + (size_t)gr * ldc + gc) = v;
            }
        }
    }
}

// ------------------------------ batch norm -----------------------------------
#define BN_ROWS 512
__global__ void bn_stats_kernel(const float* __restrict__ Z, float* __restrict__ stats) {
    int col = threadIdx.x;
    int r0 = blockIdx.x * BN_ROWS;
    int r1 = min(r0 + BN_ROWS, N_NODES);
    float s = 0.f, sq = 0.f;
    for (int r = r0; r < r1; r++) {
        float v = Z[(size_t)r * HID + col];
        s += v;
        sq = fmaf(v, v, sq);
    }
    atomicAdd(&stats[col], s);
    atomicAdd(&stats[HID + col], sq);
}

__global__ void bn_apply_kernel(const float* __restrict__ Z,
                                const float* __restrict__ stats,
                                const float* __restrict__ gamma,
                                const float* __restrict__ beta,
                                float* __restrict__ out, int ostride) {
    int idx = blockIdx.x * blockDim.x + threadIdx.x;
    if (idx >= N_NODES * HID) return;
    int row = idx / HID, col = idx - row * HID;
    float inv_n = 1.f / (float)N_NODES;
    float mu = stats[col] * inv_n;
    float var = stats[HID + col] * inv_n - mu * mu;
    float scale = rsqrtf(var + BN_EPSF) * gamma[col];
    out[(size_t)row * ostride + col] = (Z[idx] - mu) * scale + beta[col];
}

// ------------------------------- pooling -------------------------------------
#define POOL_ROWS 1024
__global__ void pool_sum_kernel(const float* __restrict__ emb,
                                const int* __restrict__ batch,
                                float* __restrict__ gsum) {
    int col = blockIdx.y * 128 + threadIdx.x;
    int r0 = blockIdx.x * POOL_ROWS;
    int r1 = min(r0 + POOL_ROWS, N_NODES);
    float acc = 0.f;
    int cur = batch[r0];
    for (int r = r0; r < r1; r++) {
        int b = batch[r];
        if (b != cur) {
            atomicAdd(&gsum[(size_t)cur * EMBW + col], acc);
            acc = 0.f; cur = b;
        }
        acc += emb[(size_t)r * EMBW + col];
    }
    atomicAdd(&gsum[(size_t)cur * EMBW + col], acc);
}

__global__ void count_kernel(const int* __restrict__ batch, float* __restrict__ cnt) {
    __shared__ int hist[N_GRAPH];
    int tid = threadIdx.x;
    if (tid < N_GRAPH) hist[tid] = 0;
    __syncthreads();
    for (int i = blockIdx.x * blockDim.x + tid; i < N_NODES; i += gridDim.x * blockDim.x)
        atomicAdd(&hist[batch[i]], 1);
    __syncthreads();
    if (tid < N_GRAPH && hist[tid]) atomicAdd(&cnt[tid], (float)hist[tid]);
}

__global__ void pool_div_kernel(float* __restrict__ gsum, const float* __restrict__ cnt) {
    int i = blockIdx.x * blockDim.x + threadIdx.x;
    if (i >= N_GRAPH * EMBW) return;
    int g = i / EMBW;
    gsum[i] = gsum[i] / fmaxf(cnt[g], 1.f);
}

// ------------------------- small MLP (classifier) -----------------------------
__global__ void small_mlp_kernel(const float* __restrict__ A,
                                 const float* __restrict__ B,
                                 const float* __restrict__ bias,
                                 float* __restrict__ C,
                                 int M, int N, int K, int relu) {
    int idx = blockIdx.x * blockDim.x + threadIdx.x;
    if (idx >= M * N) return;
    int i = idx / N, j = idx - i * N;
    float s = bias[j];
    const float* a = A + (size_t)i * K;
    for (int k = 0; k < K; k++) s = fmaf(a[k], B[(size_t)k * N + j], s);
    if (relu) s = fmaxf(s, 0.f);
    C[idx] = s;
}

__global__ void logsoftmax_kernel(const float* __restrict__ in, float* __restrict__ out) {
    int g = blockIdx.x;
    int lane = threadIdx.x;
    float v = (lane < NCLS) ? in[g * NCLS + lane] : -INFINITY;
    float m = v;
#pragma unroll
    for (int o = 16; o > 0; o >>= 1) m = fmaxf(m, __shfl_xor_sync(0xffffffffu, m, o));
    float e = (lane < NCLS) ? expf(v - m) : 0.f;
    float s = e;
#pragma unroll
    for (int o = 16; o > 0; o >>= 1) s += __shfl_xor_sync(0xffffffffu, s, o);
    if (lane < NCLS) out[g * NCLS + lane] = v - m - logf(s);
}

// --------------------------- edge predictor ----------------------------------
__global__ void edge_gather_kernel(const int* __restrict__ ce,
                                   const float* __restrict__ P,
                                   const float* __restrict__ b,
                                   float* __restrict__ U) {
    int warp = (blockIdx.x * blockDim.x + threadIdx.x) >> 5;
    int lane = threadIdx.x & 31;
    if (warp >= NCANDE) return;
    int c0 = __ldg(&ce[warp]);
    int c1 = __ldg(&ce[NCANDE + warp]);
    const float4* p0 = (const float4*)(P + (size_t)c0 * 512);
    const float4* p1 = (const float4*)(P + (size_t)c1 * 512 + 256);
    float4* u = (float4*)(U + (size_t)warp * 256);
#pragma unroll
    for (int i = 0; i < 2; i++) {
        int q = lane + i * 32;
        float4 a = __ldg(&p0[q]);
        float4 c = __ldg(&p1[q]);
        float4 bb = *(const float4*)(b + q * 4);
        float4 r;
        r.x = fmaxf(a.x + c.x + bb.x, 0.f);
        r.y = fmaxf(a.y + c.y + bb.y, 0.f);
        r.z = fmaxf(a.z + c.z + bb.z, 0.f);
        r.w = fmaxf(a.w + c.w + bb.w, 0.f);
        u[q] = r;
    }
}

__global__ void edge_score_kernel(const float* __restrict__ U2,
                                  const float* __restrict__ w,
                                  const float* __restrict__ b,
                                  float* __restrict__ out) {
    int warp = (blockIdx.x * blockDim.x + threadIdx.x) >> 5;
    int lane = threadIdx.x & 31;
    if (warp >= NCANDE) return;
    float4 a = __ldg((const float4*)(U2 + (size_t)warp * 128) + lane);
    float4 wv = __ldg((const float4*)w + lane);
    float s = a.x * wv.x + a.y * wv.y + a.z * wv.z + a.w * wv.w;
#pragma unroll
    for (int o = 16; o > 0; o >>= 1) s += __shfl_xor_sync(0xffffffffu, s, o);
    if (lane == 0) {
        float z = s + b[0];
        out[warp] = 1.f / (1.f + expf(-z));
    }
}

// --------------------------------- host --------------------------------------
static void* sym_addr(const void* sym) {
    void* p = nullptr;
    cudaGetSymbolAddress(&p, sym);
    return p;
}

extern "C" void kernel_launch(void* const* d_in, const int* in_sizes, int n_in,
                              void* d_out, int out_size) {
    (void)n_in; (void)out_size;
    const float *x, *cW1, *cb1, *cW2, *cb2, *cgamma, *cbeta, *ceps;
    const float *ncW1, *ncb1, *ncW2, *ncb2, *ncW3, *ncb3, *ncW4, *ncb4;
    const float *epW1, *epb1, *epW2, *epb2, *epW3, *epb3;
    const int *edge_index, *batch, *cand;
    bool dict_order = (in_sizes[1] == 2 * N_EDGES);
    if (dict_order) {
        x          = (const float*)d_in[0];
        edge_index = (const int*)  d_in[1];
        batch      = (const int*)  d_in[2];
        cand       = (const int*)  d_in[3];
        cW1 = (const float*)d_in[4];  cb1 = (const float*)d_in[5];
        cW2 = (const float*)d_in[6];  cb2 = (const float*)d_in[7];
        cgamma = (const float*)d_in[8]; cbeta = (const float*)d_in[9];
        ceps = (const float*)d_in[10];
        ncW1 = (const float*)d_in[11]; ncb1 = (const float*)d_in[12];
        ncW2 = (const float*)d_in[13]; ncb2 = (const float*)d_in[14];
        ncW3 = (const float*)d_in[15]; ncb3 = (const float*)d_in[16];
        ncW4 = (const float*)d_in[17]; ncb4 = (const float*)d_in[18];
        epW1 = (const float*)d_in[19]; epb1 = (const float*)d_in[20];
        epW2 = (const float*)d_in[21]; epb2 = (const float*)d_in[22];
        epW3 = (const float*)d_in[23]; epb3 = (const float*)d_in[24];
    } else {
        x = (const float*)d_in[0];
        cW1 = (const float*)d_in[1];  cb1 = (const float*)d_in[2];
        cW2 = (const float*)d_in[3];  cb2 = (const float*)d_in[4];
        cgamma = (const float*)d_in[5]; cbeta = (const float*)d_in[6];
        ceps = (const float*)d_in[7];
        ncW1 = (const float*)d_in[8];  ncb1 = (const float*)d_in[9];
        ncW2 = (const float*)d_in[10]; ncb2 = (const float*)d_in[11];
        ncW3 = (const float*)d_in[12]; ncb3 = (const float*)d_in[13];
        ncW4 = (const float*)d_in[14]; ncb4 = (const float*)d_in[15];
        epW1 = (const float*)d_in[16]; epb1 = (const float*)d_in[17];
        epW2 = (const float*)d_in[18]; epb2 = (const float*)d_in[19];
        epW3 = (const float*)d_in[20]; epb3 = (const float*)d_in[21];
        edge_index = (const int*)d_in[22];
        batch      = (const int*)d_in[23];
        cand       = (const int*)d_in[24];
    }
    float* out = (float*)d_out;

    float* p_emb  = (float*)sym_addr(g_emb);
    float* p_agg  = (float*)sym_addr(g_agg);
    float* p_z1   = (float*)sym_addr(g_z1);
    float* p_z2   = (float*)sym_addr(g_z2);
    float* p_P    = (float*)sym_addr(g_P);
    float* p_u    = (float*)sym_addr(g_u);
    float* p_u2   = (float*)sym_addr(g_u2);
    float* p_st   = (float*)sym_addr(g_stats);
    float* p_gemb = (float*)sym_addr(g_gemb);
    float* p_cnt  = (float*)sym_addr(g_cnt);
    float* p_t1   = (float*)sym_addr(g_t1);
    float* p_t2   = (float*)sym_addr(g_t2);
    float* p_t3   = (float*)sym_addr(g_t3);
    float* p_lg   = (float*)sym_addr(g_logits);
    int* p_deg  = (int*)sym_addr(g_deg);
    int* p_off  = (int*)sym_addr(g_off);
    int* p_pos  = (int*)sym_addr(g_pos);
    int* p_csr  = (int*)sym_addr(g_csr);
    int* p_bsum = (int*)sym_addr(g_bsum);

    const int T = 256;
    dim3 gemmGrid128(1, (N_NODES + 127) / 128);
    dim3 gemmGrid256(2, (N_NODES + 127) / 128);
    const int nScanBlocks = (N_NODES + SCAN_B - 1) / SCAN_B;   // 98

    // ================= CSR build (once; graph constant across layers) ==========
    zeroi_kernel<<<(N_NODES + T - 1) / T, T>>>(p_deg, N_NODES);
    hist_kernel<<<(N_EDGES + T - 1) / T, T>>>(edge_index, p_deg);
    scan_block_kernel<<<nScanBlocks, SCAN_B>>>(p_deg, p_off, p_bsum, N_NODES);
    scan_bsum_kernel<<<1, 128>>>(p_bsum, nScanBlocks);
    scan_add_kernel<<<(N_NODES + T) / T, T>>>(p_off, p_bsum, p_pos, N_NODES);
    csr_fill_kernel<<<(N_EDGES + T - 1) / T, T>>>(edge_index, p_pos, p_csr);

    // ================= GIN layers =================
    for (int l = 0; l < NLAY; l++) {
        const float* h = (l == 0) ? x : (p_emb + (l - 1) * HID);
        int hstride = (l == 0) ? HID : EMBW;

        gin_gather_kernel<<<(N_NODES * 32 + T - 1) / T, T>>>(p_off, p_csr, h, hstride,
                                                             ceps, l, p_agg);

        tf32_gemm_kernel<<<gemmGrid128, 256>>>(p_agg, HID, cW1 + (size_t)l * HID * HID, HID,
                                               cb1 + l * HID, p_z1, HID,
                                               N_NODES, HID, HID, 1);
        tf32_gemm_kernel<<<gemmGrid128, 256>>>(p_z1, HID, cW2 + (size_t)l * HID * HID, HID,
                                               cb2 + l * HID, p_z2, HID,
                                               N_NODES, HID, HID, 1);

        zero_kernel<<<1, 256>>>(p_st, 2 * HID);
        bn_stats_kernel<<<(N_NODES + BN_ROWS - 1) / BN_ROWS, HID>>>(p_z2, p_st);
        bn_apply_kernel<<<(N_NODES * HID + T - 1) / T, T>>>(
            p_z2, p_st, cgamma + l * HID, cbeta + l * HID, p_emb + l * HID, EMBW);
    }

    // ================= global mean pool =================
    zero_kernel<<<(N_GRAPH * EMBW + T - 1) / T, T>>>(p_gemb, N_GRAPH * EMBW);
    zero_kernel<<<1, 64>>>(p_cnt, N_GRAPH);
    {
        dim3 pg((N_NODES + POOL_ROWS - 1) / POOL_ROWS, EMBW / 128);
        pool_sum_kernel<<<pg, 128>>>(p_emb, batch, p_gemb);
    }
    count_kernel<<<128, 256>>>(batch, p_cnt);
    pool_div_kernel<<<(N_GRAPH * EMBW + T - 1) / T, T>>>(p_gemb, p_cnt);

    // ================= node classifier =================
    small_mlp_kernel<<<(N_GRAPH * 256 + T - 1) / T, T>>>(p_gemb, ncW1, ncb1, p_t1,
                                                         N_GRAPH, 256, EMBW, 1);
    small_mlp_kernel<<<(N_GRAPH * 128 + T - 1) / T, T>>>(p_t1, ncW2, ncb2, p_t2,
                                                         N_GRAPH, 128, 256, 1);
    small_mlp_kernel<<<(N_GRAPH * 128 + T - 1) / T, T>>>(p_t2, ncW3, ncb3, p_t3,
                                                         N_GRAPH, 128, 128, 1);
    small_mlp_kernel<<<(N_GRAPH * NCLS + T - 1) / T, T>>>(p_t3, ncW4, ncb4, p_lg,
                                                          N_GRAPH, NCLS, 128, 0);
    logsoftmax_kernel<<<N_GRAPH, 32>>>(p_lg, out);

    // ================= edge predictor =================
    tf32_gemm_kernel<<<gemmGrid256, 256>>>(p_emb, EMBW, epW1, 256, nullptr,
                                           p_P, 512, N_NODES, 256, EMBW, 0);
    tf32_gemm_kernel<<<gemmGrid256, 256>>>(p_emb, EMBW, epW1 + (size_t)512 * 256, 256, nullptr,
                                           p_P + 256, 512, N_NODES, 256, EMBW, 0);
    edge_gather_kernel<<<(NCANDE * 32 + T - 1) / T, T>>>(cand, p_P, epb1, p_u);
    tf32_gemm_kernel<<<gemmGrid128, 256>>>(p_u, 256, epW2, 128, epb2, p_u2, 128,
                                           NCANDE, 128, 256, 1);
    edge_score_kernel<<<(NCANDE * 32 + T - 1) / T, T>>>(p_u2, epW3, epb3,
                                                        out + N_GRAPH * NCLS);
}